// round 15
// baseline (speedup 1.0000x reference)
#include <cuda_runtime.h>
#include <math.h>

#define N_ATOMS 2048
#define HID     32
#define CUTOFF  2.5f
#define CUTOFF2 6.25f
#define JCHUNK  16
#define LUT_B   256           // smem lerp LUT bins over d in [0, CUTOFF]; +1 guard
#define NDIAG   128           // 8 diagonal tiles x 16 chunks, weight 0.5
#define NBLK    576           // 128 diag + 448 off-diag

__device__ double   g_energy = 0.0;
__device__ unsigned g_done   = 0;

// cumulative off-diagonal chunk counts per i-tile (count ti = 112 - 16*ti)
__constant__ int c_off[9] = {0, 112, 208, 288, 352, 400, 432, 448, 448};

__device__ __forceinline__ float tanh_fast(float x) {
    float y;
    asm("tanh.approx.f32 %0, %1;" : "=f"(y) : "f"(x));
    return y;
}
__device__ __forceinline__ float sqrt_fast(float x) {
    float y;
    asm("sqrt.approx.f32 %0, %1;" : "=f"(y) : "f"(x));
    return y;
}

__device__ __forceinline__ float mlp_eval(float x,
    const float* __restrict__ W1, const float* __restrict__ b1,
    const float* __restrict__ W2, float b2v)
{
    float f = b2v;
    #pragma unroll
    for (int k = 0; k < HID; k++)
        f = fmaf(tanh_fast(fmaf(x, W1[k], b1[k])), W2[k], f);
    return f;
}

__global__ __launch_bounds__(256, 4) void pair_kernel(
    const float* __restrict__ xyz,
    const float* __restrict__ cell,
    const float* __restrict__ W1,
    const float* __restrict__ b1,
    const float* __restrict__ W2,
    const float* __restrict__ b2,
    float* __restrict__ out)
{
    __shared__ float  sf[LUT_B + 1];      // f(d) at bin edges 0..LUT_B
    __shared__ float2 slut[LUT_B + 1];    // (f, df) per bin + guard
    __shared__ float4 sj[JCHUNK];
    __shared__ float  swarp[8];

    const int tid = threadIdx.x;
    const int blk = blockIdx.x;

    // ---- block -> (i_tile, j0, weight) -------------------------------
    int   ti, j0;
    float w;
    if (blk < NDIAG) {                    // diagonal band: full 256x16, w=0.5
        ti = blk >> 4;
        j0 = ti * 256 + (blk & 15) * JCHUNK;
        w  = 0.5f;
    } else {                              // strictly above the diagonal, w=1
        int b = blk - NDIAG;
        ti = 0;
        #pragma unroll
        for (int k = 0; k < 7; k++)
            if (b >= c_off[k + 1]) ti = k + 1;
        j0 = (ti + 1) * 256 + (b - c_off[ti]) * JCHUNK;
        w  = 1.0f;
    }
    const int i = ti * 256 + tid;

    // ---- Phase 1: build per-block smem LUT ---------------------------
    {
        const float step = CUTOFF / (float)LUT_B;
        const float b2v  = b2[0];
        sf[tid] = mlp_eval((float)tid * step, W1, b1, W2, b2v);
        if (tid == 0)                      // fencepost: edge LUT_B = f(CUTOFF)
            sf[LUT_B] = mlp_eval(CUTOFF, W1, b1, W2, b2v);
    }
    // stage j-chunk concurrently (different smem array, no conflict)
    if (tid >= 256 - JCHUNK) {
        int jj = tid - (256 - JCHUNK);
        int j  = j0 + jj;
        sj[jj] = make_float4(xyz[3*j], xyz[3*j+1], xyz[3*j+2], 0.f);
    }
    const float Lx = cell[0], Ly = cell[1], Lz = cell[2];
    const float xi = xyz[3*i], yi = xyz[3*i+1], zi = xyz[3*i+2];
    __syncthreads();

    if (tid < LUT_B)
        slut[tid] = make_float2(sf[tid], sf[tid + 1] - sf[tid]);
    if (tid == 0)
        slut[LUT_B] = make_float2(0.f, 0.f);   // guard: misses add exactly 0
    __syncthreads();

    // ---- Phase 2: pair loop ------------------------------------------
    const float dscale = (float)LUT_B / CUTOFF;   // d -> bin
    const float tmax   = (float)LUT_B;            // guard bin

    float acc = 0.0f;

    #pragma unroll
    for (int jj = 0; jj < JCHUNK; jj++) {
        float4 p = sj[jj];
        // MIC magnitude per dim: |dx_mic| = min(|dx|, L - |dx|)  (|dx| < L)
        float ax = fabsf(p.x - xi);
        float ay = fabsf(p.y - yi);
        float az = fabsf(p.z - zi);
        float wx = fminf(ax, Lx - ax);
        float wy = fminf(ay, Ly - ay);
        float wz = fminf(az, Lz - az);
        float dsq = fmaf(wx, wx, fmaf(wy, wy, wz * wz));

        float d  = sqrt_fast(dsq);
        float t  = fminf(d * dscale, tmax);    // miss -> guard bin (0,0)
        int   it = (int)t;
        float fr = t - (float)it;
        float2 e = slut[it];                   // LDS.64
        acc += fmaf(fr, e.y, e.x);             // unconditional
    }

    // self-pair (d=0 -> bin 0 contributes f(0)), once per atom in its diag chunk
    if ((unsigned)(i - j0) < (unsigned)JCHUNK)
        acc -= sf[0];

    acc *= w;

    // ---- Reduce + finish ---------------------------------------------
    #pragma unroll
    for (int off = 16; off > 0; off >>= 1)
        acc += __shfl_down_sync(0xFFFFFFFFu, acc, off);

    const int lane = tid & 31;
    const int warp = tid >> 5;
    if (lane == 0) swarp[warp] = acc;
    __syncthreads();

    if (warp == 0) {
        float v = (lane < 8) ? swarp[lane] : 0.0f;
        #pragma unroll
        for (int off = 4; off > 0; off >>= 1)
            v += __shfl_down_sync(0xFFFFFFFFu, v, off);
        if (lane == 0) {
            atomicAdd(&g_energy, (double)v);
            __threadfence();
            unsigned old = atomicAdd(&g_done, 1u);
            if (old == NBLK - 1) {
                __threadfence();
                double esum = __longlong_as_double(
                    atomicExch((unsigned long long*)&g_energy, 0ULL));
                out[0] = (float)esum;          // triangle: no halving
                __threadfence();
                atomicExch(&g_done, 0u);
            }
        }
    }
}

extern "C" void kernel_launch(void* const* d_in, const int* in_sizes, int n_in,
                              void* d_out, int out_size)
{
    const float* xyz  = (const float*)d_in[0];
    const float* cell = (const float*)d_in[1];
    const float* W1   = (const float*)d_in[2];
    const float* b1   = (const float*)d_in[3];
    const float* W2   = (const float*)d_in[4];
    const float* b2   = (const float*)d_in[5];
    float* out = (float*)d_out;

    pair_kernel<<<NBLK, 256>>>(xyz, cell, W1, b1, W2, b2, out);
}

// round 16
// speedup vs baseline: 1.2656x; 1.2656x over previous
#include <cuda_runtime.h>
#include <math.h>

#define N_ATOMS 2048
#define HID     32
#define CUTOFF  2.5f
#define CUTOFF2 6.25f
#define JCHUNK  16
#define LUT_B   255           // bins over d in [0,CUTOFF]; 256 edges = 1 per thread
#define NDIAG   128           // 8 diagonal tiles x 16 chunks, weight 0.5
#define NBLK    576           // 128 diag + 448 off-diag

__device__ double   g_energy = 0.0;
__device__ unsigned g_done   = 0;

// cumulative off-diagonal chunk counts per i-tile (count ti = 112 - 16*ti)
__constant__ int c_off[9] = {0, 112, 208, 288, 352, 400, 432, 448, 448};

__device__ __forceinline__ float tanh_fast(float x) {
    float y;
    asm("tanh.approx.f32 %0, %1;" : "=f"(y) : "f"(x));
    return y;
}
__device__ __forceinline__ float sqrt_fast(float x) {
    float y;
    asm("sqrt.approx.f32 %0, %1;" : "=f"(y) : "f"(x));
    return y;
}

__global__ __launch_bounds__(256, 4) void pair_kernel(
    const float* __restrict__ xyz,
    const float* __restrict__ cell,
    const float* __restrict__ W1,
    const float* __restrict__ b1,
    const float* __restrict__ W2,
    const float* __restrict__ b2,
    float* __restrict__ out)
{
    __shared__ float  sf[LUT_B + 1];      // f(d) at edges 0..255
    __shared__ float2 slut[LUT_B + 1];    // bins 0..254 = (f, df); 255 = guard (0,0)
    __shared__ float4 sj[JCHUNK];
    __shared__ float  swarp[8];

    const int tid  = threadIdx.x;
    const int lane = tid & 31;
    const int blk  = blockIdx.x;

    // ---- block -> (i_tile, j0, weight) -------------------------------
    int   ti, j0;
    float w;
    if (blk < NDIAG) {                    // diagonal band: full 256x16, w=0.5
        ti = blk >> 4;
        j0 = ti * 256 + (blk & 15) * JCHUNK;
        w  = 0.5f;
    } else {                              // strictly above the diagonal, w=1
        int b = blk - NDIAG;
        ti = 0;
        #pragma unroll
        for (int k = 0; k < 7; k++)
            if (b >= c_off[k + 1]) ti = k + 1;
        j0 = (ti + 1) * 256 + (b - c_off[ti]) * JCHUNK;
        w  = 1.0f;
    }
    const int i = ti * 256 + tid;

    // ---- Phase 1: build per-block smem LUT via lane-distributed weights
    {
        // lane k holds weights of hidden unit k (3 LDGs per thread total)
        const float w1l = W1[lane];
        const float b1l = b1[lane];
        const float w2l = W2[lane];
        const float b2v = b2[0];

        const float x = (float)tid * (CUTOFF / (float)LUT_B);  // tid 255 -> CUTOFF
        float f = b2v;
        #pragma unroll
        for (int k = 0; k < HID; k++) {
            float w1k = __shfl_sync(0xFFFFFFFFu, w1l, k);
            float b1k = __shfl_sync(0xFFFFFFFFu, b1l, k);
            float w2k = __shfl_sync(0xFFFFFFFFu, w2l, k);
            f = fmaf(tanh_fast(fmaf(x, w1k, b1k)), w2k, f);
        }
        sf[tid] = f;    // all 256 edges written, one per thread
    }
    // stage j-chunk concurrently (different smem array)
    if (tid >= 256 - JCHUNK) {
        int jj = tid - (256 - JCHUNK);
        int j  = j0 + jj;
        sj[jj] = make_float4(xyz[3*j], xyz[3*j+1], xyz[3*j+2], 0.f);
    }
    const float Lx = cell[0], Ly = cell[1], Lz = cell[2];
    const float xi = xyz[3*i], yi = xyz[3*i+1], zi = xyz[3*i+2];
    __syncthreads();

    if (tid < LUT_B)
        slut[tid] = make_float2(sf[tid], sf[tid + 1] - sf[tid]);
    else                                   // tid == 255: guard bin
        slut[LUT_B] = make_float2(0.f, 0.f);
    __syncthreads();

    // ---- Phase 2: pair loop ------------------------------------------
    const float dscale = (float)LUT_B / CUTOFF;   // d -> bin
    const float tmax   = (float)LUT_B;            // guard bin index

    float acc = 0.0f;

    #pragma unroll
    for (int jj = 0; jj < JCHUNK; jj++) {
        float4 p = sj[jj];
        // MIC magnitude per dim: |dx_mic| = min(|dx|, L - |dx|)  (|dx| < L)
        float ax = fabsf(p.x - xi);
        float ay = fabsf(p.y - yi);
        float az = fabsf(p.z - zi);
        float wx = fminf(ax, Lx - ax);
        float wy = fminf(ay, Ly - ay);
        float wz = fminf(az, Lz - az);
        float dsq = fmaf(wx, wx, fmaf(wy, wy, wz * wz));

        float d  = sqrt_fast(dsq);
        float t  = fminf(d * dscale, tmax);    // miss -> guard bin (0,0)
        int   it = (int)t;
        float fr = t - (float)it;
        float2 e = slut[it];                   // LDS.64
        acc += fmaf(fr, e.y, e.x);             // unconditional
    }

    // self-pair (d=0 -> bin 0 contributes f(0)), once per atom in its diag chunk
    if ((unsigned)(i - j0) < (unsigned)JCHUNK)
        acc -= sf[0];

    acc *= w;

    // ---- Reduce + finish ---------------------------------------------
    #pragma unroll
    for (int off = 16; off > 0; off >>= 1)
        acc += __shfl_down_sync(0xFFFFFFFFu, acc, off);

    const int warp = tid >> 5;
    if (lane == 0) swarp[warp] = acc;
    __syncthreads();

    if (warp == 0) {
        float v = (lane < 8) ? swarp[lane] : 0.0f;
        #pragma unroll
        for (int off = 4; off > 0; off >>= 1)
            v += __shfl_down_sync(0xFFFFFFFFu, v, off);
        if (lane == 0) {
            atomicAdd(&g_energy, (double)v);
            __threadfence();
            unsigned old = atomicAdd(&g_done, 1u);
            if (old == NBLK - 1) {
                __threadfence();
                double esum = __longlong_as_double(
                    atomicExch((unsigned long long*)&g_energy, 0ULL));
                out[0] = (float)esum;          // triangle: no halving
                __threadfence();
                atomicExch(&g_done, 0u);
            }
        }
    }
}

extern "C" void kernel_launch(void* const* d_in, const int* in_sizes, int n_in,
                              void* d_out, int out_size)
{
    const float* xyz  = (const float*)d_in[0];
    const float* cell = (const float*)d_in[1];
    const float* W1   = (const float*)d_in[2];
    const float* b1   = (const float*)d_in[3];
    const float* W2   = (const float*)d_in[4];
    const float* b2   = (const float*)d_in[5];
    float* out = (float*)d_out;

    pair_kernel<<<NBLK, 256>>>(xyz, cell, W1, b1, W2, b2, out);
}